// round 3
// baseline (speedup 1.0000x reference)
#include <cuda_runtime.h>
#include <cuda_bf16.h>

#define NSN 50000
#define NE  1600000
#define CIN 11
#define HD  64
#define SPAN 1024
#define NBLK 49    // ceil(NSN / SPAN)

// ---------------- scratch (static __device__, no allocation) ----------------
__device__ int   g_hist[4][NSN];
__device__ int   g_rowstart[4][NSN];
__device__ int   g_cursor[4][NSN];
__device__ int   g_csr[4][NE];
__device__ int   g_bsum[4][64];
__device__ float g_mean1[4][NSN*CIN];
__device__ float g_mean2[4][(size_t)NSN*HD];
__device__ float g_h[2][(size_t)NSN*HD];           // layer-1 output fp32 (self term)
__device__ __nv_bfloat16 g_hbf[2][(size_t)NSN*HD]; // layer-1 output bf16 (gather)
__device__ float g_h2[2][(size_t)NSN*HD];

// ---------------- zero histogram --------------------------------------------
__global__ void k_zero_hist() {
    int i = blockIdx.x * 256 + threadIdx.x;
    if (i < NSN) {
        #pragma unroll
        for (int t = 0; t < 4; t++) g_hist[t][i] = 0;
    }
}

// ---------------- degree histogram (4 edges / thread) ------------------------
__global__ void k_hist(const int* __restrict__ d0, const int* __restrict__ d1,
                       const int* __restrict__ d2, const int* __restrict__ d3) {
    int i = blockIdx.x * 256 + threadIdx.x;     // i indexes int4 groups
    if (i >= NE / 4) return;
    int4 v0 = ((const int4*)d0)[i];
    int4 v1 = ((const int4*)d1)[i];
    int4 v2 = ((const int4*)d2)[i];
    int4 v3 = ((const int4*)d3)[i];
    atomicAdd(&g_hist[0][v0.x], 1); atomicAdd(&g_hist[0][v0.y], 1);
    atomicAdd(&g_hist[0][v0.z], 1); atomicAdd(&g_hist[0][v0.w], 1);
    atomicAdd(&g_hist[1][v1.x], 1); atomicAdd(&g_hist[1][v1.y], 1);
    atomicAdd(&g_hist[1][v1.z], 1); atomicAdd(&g_hist[1][v1.w], 1);
    atomicAdd(&g_hist[2][v2.x], 1); atomicAdd(&g_hist[2][v2.y], 1);
    atomicAdd(&g_hist[2][v2.z], 1); atomicAdd(&g_hist[2][v2.w], 1);
    atomicAdd(&g_hist[3][v3.x], 1); atomicAdd(&g_hist[3][v3.y], 1);
    atomicAdd(&g_hist[3][v3.z], 1); atomicAdd(&g_hist[3][v3.w], 1);
}

// ---------------- scan phase A: per-block sums -------------------------------
__global__ void __launch_bounds__(256) k_bsum() {
    int t = blockIdx.y;
    int base = blockIdx.x * SPAN + threadIdx.x * 4;
    int s = 0;
    #pragma unroll
    for (int u = 0; u < 4; u++) {
        int idx = base + u;
        if (idx < NSN) s += g_hist[t][idx];
    }
    #pragma unroll
    for (int off = 16; off > 0; off >>= 1)
        s += __shfl_xor_sync(0xffffffffu, s, off);
    __shared__ int ws[8];
    int lane = threadIdx.x & 31, warp = threadIdx.x >> 5;
    if (lane == 0) ws[warp] = s;
    __syncthreads();
    if (threadIdx.x == 0) {
        int tot = 0;
        #pragma unroll
        for (int w = 0; w < 8; w++) tot += ws[w];
        g_bsum[t][blockIdx.x] = tot;
    }
}

// ---------------- scan phase B: scan block sums (tiny) -----------------------
__global__ void k_sb() {
    __shared__ int sm[4][64];
    int t = threadIdx.x >> 6, j = threadIdx.x & 63;
    if (j < NBLK) sm[t][j] = g_bsum[t][j];
    __syncthreads();
    if (threadIdx.x < 4) {
        int off = 0;
        for (int i = 0; i < NBLK; i++) {
            int v = sm[threadIdx.x][i];
            sm[threadIdx.x][i] = off;
            off += v;
        }
    }
    __syncthreads();
    if (j < NBLK) g_bsum[t][j] = sm[t][j];
}

// ---------------- scan phase C: final offsets --------------------------------
__global__ void __launch_bounds__(256) k_scan2() {
    int t = blockIdx.y;
    int lane = threadIdx.x & 31, warp = threadIdx.x >> 5;
    int base = blockIdx.x * SPAN + threadIdx.x * 4;
    int v[4]; int s = 0;
    #pragma unroll
    for (int u = 0; u < 4; u++) {
        int idx = base + u;
        v[u] = (idx < NSN) ? g_hist[t][idx] : 0;
        s += v[u];
    }
    int x = s;
    #pragma unroll
    for (int off = 1; off < 32; off <<= 1) {
        int y = __shfl_up_sync(0xffffffffu, x, off);
        if (lane >= off) x += y;
    }
    __shared__ int ws[8];
    if (lane == 31) ws[warp] = x;
    __syncthreads();
    if (warp == 0 && lane < 8) {
        int w = ws[lane];
        #pragma unroll
        for (int off = 1; off < 8; off <<= 1) {
            int y = __shfl_up_sync(0xffu, w, off);
            if (lane >= off) w += y;
        }
        ws[lane] = w;
    }
    __syncthreads();
    int ex = x - s + (warp > 0 ? ws[warp - 1] : 0) + g_bsum[t][blockIdx.x];
    #pragma unroll
    for (int u = 0; u < 4; u++) {
        int idx = base + u;
        if (idx < NSN) {
            g_rowstart[t][idx] = ex;
            g_cursor[t][idx] = ex;
        }
        ex += v[u];
    }
}

// ---------------- CSR fill (4 edges / thread) --------------------------------
__global__ void k_fill(const int* __restrict__ e0, const int* __restrict__ e1,
                       const int* __restrict__ e2, const int* __restrict__ e3) {
    int t = blockIdx.y;
    int i = blockIdx.x * 256 + threadIdx.x;
    if (i >= NE / 4) return;
    const int* ei = (t == 0) ? e0 : (t == 1) ? e1 : (t == 2) ? e2 : e3;
    int4 s = ((const int4*)ei)[i];
    int4 d = ((const int4*)(ei + NE))[i];
    int p;
    p = atomicAdd(&g_cursor[t][d.x], 1); g_csr[t][p] = s.x;
    p = atomicAdd(&g_cursor[t][d.y], 1); g_csr[t][p] = s.y;
    p = atomicAdd(&g_cursor[t][d.z], 1); g_csr[t][p] = s.z;
    p = atomicAdd(&g_cursor[t][d.w], 1); g_csr[t][p] = s.w;
}

// ---------------- layer-1 gather-aggregate (warp per node,type) -------------
__global__ void __launch_bounds__(256) k_agg1(const float* __restrict__ xs,
                                              const float* __restrict__ xp) {
    int t = blockIdx.y;
    const float* x = (t >> 1) ? xp : xs;
    int warp = threadIdx.x >> 5, lane = threadIdx.x & 31;
    int n = blockIdx.x * 8 + warp;
    if (n >= NSN) return;
    int half = lane >> 4;
    int col = lane & 15;
    int base = g_rowstart[t][n];
    int cnt = g_hist[t][n];
    const int* cs = g_csr[t] + base;
    float acc = 0.f;
    for (int i = half; i < cnt; i += 2) {
        int s = cs[i];
        if (col < CIN) acc += x[(size_t)s * CIN + col];
    }
    acc += __shfl_xor_sync(0xffffffffu, acc, 16);
    float inv = 1.f / (float)(cnt > 0 ? cnt : 1);
    if (half == 0 && col < CIN) g_mean1[t][(size_t)n * CIN + col] = acc * inv;
}

// ---------------- layer-1 node update ---------------------------------------
__global__ void __launch_bounds__(256) k_l1nodes(const float* __restrict__ xs,
                                                 const float* __restrict__ xp,
                                                 const float* __restrict__ w1l,
                                                 const float* __restrict__ b1l,
                                                 const float* __restrict__ w1r) {
    int nt = blockIdx.y;
    int ta = nt ? 1 : 0;
    int tb = nt ? 3 : 2;
    const float* x = nt ? xp : xs;
    __shared__ float sA[CIN * HD], sB[CIN * HD], sR[CIN * HD], sb[HD];
    for (int i = threadIdx.x; i < CIN * HD; i += 256) {
        sA[i] = w1l[ta * CIN * HD + i];
        sB[i] = w1l[tb * CIN * HD + i];
        sR[i] = w1r[ta * CIN * HD + i] + w1r[tb * CIN * HD + i];
    }
    if (threadIdx.x < HD)
        sb[threadIdx.x] = b1l[ta * HD + threadIdx.x] + b1l[tb * HD + threadIdx.x];
    __syncthreads();

    int n = blockIdx.x * 256 + threadIdx.x;
    if (n >= NSN) return;

    float acc[HD];
    #pragma unroll
    for (int o = 0; o < HD; o++) acc[o] = sb[o];

    const float* A = g_mean1[ta] + (size_t)n * CIN;
    const float* B = g_mean1[tb] + (size_t)n * CIN;
    const float* X = x + (size_t)n * CIN;
    #pragma unroll
    for (int i = 0; i < CIN; i++) {
        float ma = A[i], mb = B[i], xv = X[i];
        const float4* wa = (const float4*)(sA + i * HD);
        const float4* wb = (const float4*)(sB + i * HD);
        const float4* wr = (const float4*)(sR + i * HD);
        #pragma unroll
        for (int o4 = 0; o4 < HD / 4; o4++) {
            float4 a = wa[o4], b = wb[o4], r = wr[o4];
            acc[o4 * 4 + 0] += ma * a.x + mb * b.x + xv * r.x;
            acc[o4 * 4 + 1] += ma * a.y + mb * b.y + xv * r.y;
            acc[o4 * 4 + 2] += ma * a.z + mb * b.z + xv * r.z;
            acc[o4 * 4 + 3] += ma * a.w + mb * b.w + xv * r.w;
        }
    }
    float4* out = (float4*)(g_h[nt] + (size_t)n * HD);
    __nv_bfloat162* outb = (__nv_bfloat162*)(g_hbf[nt] + (size_t)n * HD);
    #pragma unroll
    for (int o4 = 0; o4 < HD / 4; o4++) {
        float4 v;
        v.x = fmaxf(acc[o4 * 4 + 0], 0.f);
        v.y = fmaxf(acc[o4 * 4 + 1], 0.f);
        v.z = fmaxf(acc[o4 * 4 + 2], 0.f);
        v.w = fmaxf(acc[o4 * 4 + 3], 0.f);
        out[o4] = v;
        outb[o4 * 2]     = __floats2bfloat162_rn(v.x, v.y);
        outb[o4 * 2 + 1] = __floats2bfloat162_rn(v.z, v.w);
    }
}

// ---------------- layer-2 gather-aggregate (bf16, warp per node,type) -------
__global__ void __launch_bounds__(256) k_agg2() {
    int t = blockIdx.y;
    int stype = t >> 1;
    int warp = threadIdx.x >> 5, lane = threadIdx.x & 31;
    int n = blockIdx.x * 8 + warp;
    if (n >= NSN) return;
    int base = g_rowstart[t][n];
    int cnt = g_hist[t][n];
    const int* cs = g_csr[t] + base;
    const __nv_bfloat162* h2 = (const __nv_bfloat162*)g_hbf[stype];  // row stride 32
    float a0 = 0.f, a1 = 0.f;
    int i = 0;
    for (; i + 4 <= cnt; i += 4) {
        int s0 = cs[i], s1 = cs[i + 1], s2 = cs[i + 2], s3 = cs[i + 3];
        __nv_bfloat162 v0 = h2[(size_t)s0 * 32 + lane];
        __nv_bfloat162 v1 = h2[(size_t)s1 * 32 + lane];
        __nv_bfloat162 v2 = h2[(size_t)s2 * 32 + lane];
        __nv_bfloat162 v3 = h2[(size_t)s3 * 32 + lane];
        a0 += __low2float(v0) + __low2float(v1) + __low2float(v2) + __low2float(v3);
        a1 += __high2float(v0) + __high2float(v1) + __high2float(v2) + __high2float(v3);
    }
    for (; i < cnt; i++) {
        __nv_bfloat162 v = h2[(size_t)cs[i] * 32 + lane];
        a0 += __low2float(v);
        a1 += __high2float(v);
    }
    float inv = 1.f / (float)(cnt > 0 ? cnt : 1);
    float2 m; m.x = a0 * inv; m.y = a1 * inv;
    ((float2*)(g_mean2[t] + (size_t)n * HD))[lane] = m;
}

// ---------------- layer-2 node update ---------------------------------------
__global__ void __launch_bounds__(256) k_l2nodes(const float* __restrict__ w2l,
                                                 const float* __restrict__ b2l,
                                                 const float* __restrict__ w2r) {
    int nt = blockIdx.y;
    int ta = nt ? 1 : 0;
    int tb = nt ? 3 : 2;
    __shared__ float sA[HD * HD], sB[HD * HD], sR[HD * HD];
    for (int i = threadIdx.x; i < HD * HD; i += 256) {
        sA[i] = w2l[ta * HD * HD + i];
        sB[i] = w2l[tb * HD * HD + i];
        sR[i] = w2r[ta * HD * HD + i] + w2r[tb * HD * HD + i];
    }
    __syncthreads();

    int n = blockIdx.x * 256 + threadIdx.x;
    if (n >= NSN) return;

    float acc[HD];
    #pragma unroll
    for (int o = 0; o < HD; o++) acc[o] = b2l[ta * HD + o] + b2l[tb * HD + o];

    const float4* A4 = (const float4*)(g_mean2[ta] + (size_t)n * HD);
    const float4* B4 = (const float4*)(g_mean2[tb] + (size_t)n * HD);
    const float4* H4 = (const float4*)(g_h[nt] + (size_t)n * HD);

    #pragma unroll
    for (int g = 0; g < HD / 4; g++) {
        float4 mav = A4[g], mbv = B4[g], hhv = H4[g];
        float fa[4] = {mav.x, mav.y, mav.z, mav.w};
        float fb[4] = {mbv.x, mbv.y, mbv.z, mbv.w};
        float fh[4] = {hhv.x, hhv.y, hhv.z, hhv.w};
        #pragma unroll
        for (int u = 0; u < 4; u++) {
            int k = g * 4 + u;
            const float4* wa = (const float4*)(sA + k * HD);
            const float4* wb = (const float4*)(sB + k * HD);
            const float4* wr = (const float4*)(sR + k * HD);
            #pragma unroll
            for (int o4 = 0; o4 < HD / 4; o4++) {
                float4 a = wa[o4], b = wb[o4], r = wr[o4];
                acc[o4 * 4 + 0] += fa[u] * a.x + fb[u] * b.x + fh[u] * r.x;
                acc[o4 * 4 + 1] += fa[u] * a.y + fb[u] * b.y + fh[u] * r.y;
                acc[o4 * 4 + 2] += fa[u] * a.z + fb[u] * b.z + fh[u] * r.z;
                acc[o4 * 4 + 3] += fa[u] * a.w + fb[u] * b.w + fh[u] * r.w;
            }
        }
    }
    float4* out = (float4*)(g_h2[nt] + (size_t)n * HD);
    #pragma unroll
    for (int o4 = 0; o4 < HD / 4; o4++) {
        float4 v;
        v.x = fmaxf(acc[o4 * 4 + 0], 0.f);
        v.y = fmaxf(acc[o4 * 4 + 1], 0.f);
        v.z = fmaxf(acc[o4 * 4 + 2], 0.f);
        v.w = fmaxf(acc[o4 * 4 + 3], 0.f);
        out[o4] = v;
    }
}

// ---------------- final linear heads ----------------------------------------
__global__ void k_final(const float* __restrict__ wls, const float* __restrict__ bls,
                        const float* __restrict__ wlp, const float* __restrict__ blp,
                        float* __restrict__ out) {
    int n = blockIdx.x * 256 + threadIdx.x;
    if (n >= 2 * NSN) return;
    int nt = (n < NSN) ? 0 : 1;
    int m = nt ? n - NSN : n;
    const float4* h4 = (const float4*)(g_h2[nt] + (size_t)m * HD);
    const float* w = nt ? wlp : wls;
    float acc = nt ? blp[0] : bls[0];
    #pragma unroll
    for (int g = 0; g < 16; g++) {
        float4 v = h4[g];
        acc += v.x * w[g * 4] + v.y * w[g * 4 + 1] + v.z * w[g * 4 + 2] + v.w * w[g * 4 + 3];
    }
    out[n] = acc;
}

// ---------------- launch ----------------------------------------------------
extern "C" void kernel_launch(void* const* d_in, const int* in_sizes, int n_in,
                              void* d_out, int out_size) {
    const float* xs  = (const float*)d_in[0];
    const float* xp  = (const float*)d_in[1];
    const float* w1l = (const float*)d_in[2];
    const float* b1l = (const float*)d_in[3];
    const float* w1r = (const float*)d_in[4];
    const float* w2l = (const float*)d_in[5];
    const float* b2l = (const float*)d_in[6];
    const float* w2r = (const float*)d_in[7];
    const float* wls = (const float*)d_in[8];
    const float* bls = (const float*)d_in[9];
    const float* wlp = (const float*)d_in[10];
    const float* blp = (const float*)d_in[11];
    const int* ss = (const int*)d_in[12];
    const int* sp = (const int*)d_in[13];
    const int* ps = (const int*)d_in[14];
    const int* pp = (const int*)d_in[15];
    float* out = (float*)d_out;

    k_zero_hist<<<(NSN + 255) / 256, 256>>>();
    k_hist<<<(NE / 4 + 255) / 256, 256>>>(ss + NE, sp + NE, ps + NE, pp + NE);
    k_bsum<<<dim3(NBLK, 4), 256>>>();
    k_sb<<<1, 256>>>();
    k_scan2<<<dim3(NBLK, 4), 256>>>();
    k_fill<<<dim3((NE / 4 + 255) / 256, 4), 256>>>(ss, sp, ps, pp);
    k_agg1<<<dim3((NSN + 7) / 8, 4), 256>>>(xs, xp);
    k_l1nodes<<<dim3((NSN + 255) / 256, 2), 256>>>(xs, xp, w1l, b1l, w1r);
    k_agg2<<<dim3((NSN + 7) / 8, 4), 256>>>();
    k_l2nodes<<<dim3((NSN + 255) / 256, 2), 256>>>(w2l, b2l, w2r);
    k_final<<<(2 * NSN + 255) / 256, 256>>>(wls, bls, wlp, blp, out);
}

// round 4
// speedup vs baseline: 1.4339x; 1.4339x over previous
#include <cuda_runtime.h>
#include <cuda_bf16.h>

#define NSN 50000
#define NE  1600000
#define CIN 11
#define HD  64
#define SPAN 1024
#define NBLK 49    // ceil(NSN / SPAN)

// ---------------- scratch (static __device__, no allocation) ----------------
__device__ int   g_hist[4][NSN];
__device__ int   g_rowstart[4][NSN];
__device__ int   g_cursor[4][NSN];
__device__ int   g_csr[4][NE];
__device__ int   g_bsum[4][64];
__device__ float g_mean1[4][NSN*CIN];
__device__ float g_mean2[4][(size_t)NSN*HD];
__device__ float g_h[2][(size_t)NSN*HD];           // layer-1 output fp32 (self term)
__device__ __nv_bfloat16 g_hbf[2][(size_t)NSN*HD]; // layer-1 output bf16 (gather)
__device__ float g_h2[2][(size_t)NSN*HD];

// ---------------- zero histogram --------------------------------------------
__global__ void k_zero_hist() {
    int i = blockIdx.x * 256 + threadIdx.x;
    if (i < NSN) {
        #pragma unroll
        for (int t = 0; t < 4; t++) g_hist[t][i] = 0;
    }
}

// ---------------- degree histogram (scalar, 1 edge / thread — R2 form) ------
__global__ void k_hist(const int* __restrict__ d0, const int* __restrict__ d1,
                       const int* __restrict__ d2, const int* __restrict__ d3) {
    int e = blockIdx.x * 256 + threadIdx.x;   // NE divisible by 256
    atomicAdd(&g_hist[0][d0[e]], 1);
    atomicAdd(&g_hist[1][d1[e]], 1);
    atomicAdd(&g_hist[2][d2[e]], 1);
    atomicAdd(&g_hist[3][d3[e]], 1);
}

// ---------------- scan phase A: per-block sums -------------------------------
__global__ void __launch_bounds__(256) k_bsum() {
    int t = blockIdx.y;
    int base = blockIdx.x * SPAN + threadIdx.x * 4;
    int s = 0;
    #pragma unroll
    for (int u = 0; u < 4; u++) {
        int idx = base + u;
        if (idx < NSN) s += g_hist[t][idx];
    }
    #pragma unroll
    for (int off = 16; off > 0; off >>= 1)
        s += __shfl_xor_sync(0xffffffffu, s, off);
    __shared__ int ws[8];
    int lane = threadIdx.x & 31, warp = threadIdx.x >> 5;
    if (lane == 0) ws[warp] = s;
    __syncthreads();
    if (threadIdx.x == 0) {
        int tot = 0;
        #pragma unroll
        for (int w = 0; w < 8; w++) tot += ws[w];
        g_bsum[t][blockIdx.x] = tot;
    }
}

// ---------------- scan phase B: scan block sums (tiny) -----------------------
__global__ void k_sb() {
    __shared__ int sm[4][64];
    int t = threadIdx.x >> 6, j = threadIdx.x & 63;
    if (j < NBLK) sm[t][j] = g_bsum[t][j];
    __syncthreads();
    if (threadIdx.x < 4) {
        int off = 0;
        for (int i = 0; i < NBLK; i++) {
            int v = sm[threadIdx.x][i];
            sm[threadIdx.x][i] = off;
            off += v;
        }
    }
    __syncthreads();
    if (j < NBLK) g_bsum[t][j] = sm[t][j];
}

// ---------------- scan phase C: final offsets --------------------------------
__global__ void __launch_bounds__(256) k_scan2() {
    int t = blockIdx.y;
    int lane = threadIdx.x & 31, warp = threadIdx.x >> 5;
    int base = blockIdx.x * SPAN + threadIdx.x * 4;
    int v[4]; int s = 0;
    #pragma unroll
    for (int u = 0; u < 4; u++) {
        int idx = base + u;
        v[u] = (idx < NSN) ? g_hist[t][idx] : 0;
        s += v[u];
    }
    int x = s;
    #pragma unroll
    for (int off = 1; off < 32; off <<= 1) {
        int y = __shfl_up_sync(0xffffffffu, x, off);
        if (lane >= off) x += y;
    }
    __shared__ int ws[8];
    if (lane == 31) ws[warp] = x;
    __syncthreads();
    if (warp == 0 && lane < 8) {
        int w = ws[lane];
        #pragma unroll
        for (int off = 1; off < 8; off <<= 1) {
            int y = __shfl_up_sync(0xffu, w, off);
            if (lane >= off) w += y;
        }
        ws[lane] = w;
    }
    __syncthreads();
    int ex = x - s + (warp > 0 ? ws[warp - 1] : 0) + g_bsum[t][blockIdx.x];
    #pragma unroll
    for (int u = 0; u < 4; u++) {
        int idx = base + u;
        if (idx < NSN) {
            g_rowstart[t][idx] = ex;
            g_cursor[t][idx] = ex;
        }
        ex += v[u];
    }
}

// ---------------- CSR fill (scalar, 1 edge / thread — R2 form) ---------------
__global__ void k_fill(const int* __restrict__ e0, const int* __restrict__ e1,
                       const int* __restrict__ e2, const int* __restrict__ e3) {
    int t = blockIdx.y;
    int e = blockIdx.x * 256 + threadIdx.x;
    const int* ei = (t == 0) ? e0 : (t == 1) ? e1 : (t == 2) ? e2 : e3;
    int s = ei[e];
    int d = ei[NE + e];
    int pos = atomicAdd(&g_cursor[t][d], 1);
    g_csr[t][pos] = s;
}

// ---------------- layer-1 gather-aggregate (warp per node,type) -------------
__global__ void __launch_bounds__(256) k_agg1(const float* __restrict__ xs,
                                              const float* __restrict__ xp) {
    int t = blockIdx.y;
    const float* x = (t >> 1) ? xp : xs;
    int warp = threadIdx.x >> 5, lane = threadIdx.x & 31;
    int n = blockIdx.x * 8 + warp;
    if (n >= NSN) return;
    int half = lane >> 4;
    int col = lane & 15;
    int base = g_rowstart[t][n];
    int cnt = g_hist[t][n];
    const int* cs = g_csr[t] + base;
    float acc = 0.f;
    for (int i = half; i < cnt; i += 2) {
        int s = cs[i];
        if (col < CIN) acc += x[(size_t)s * CIN + col];
    }
    acc += __shfl_xor_sync(0xffffffffu, acc, 16);
    float inv = 1.f / (float)(cnt > 0 ? cnt : 1);
    if (half == 0 && col < CIN) g_mean1[t][(size_t)n * CIN + col] = acc * inv;
}

// ---------------- layer-1 node update (R2 form, fp32 only) ------------------
__global__ void __launch_bounds__(256) k_l1nodes(const float* __restrict__ xs,
                                                 const float* __restrict__ xp,
                                                 const float* __restrict__ w1l,
                                                 const float* __restrict__ b1l,
                                                 const float* __restrict__ w1r) {
    int nt = blockIdx.y;
    int ta = nt ? 1 : 0;
    int tb = nt ? 3 : 2;
    const float* x = nt ? xp : xs;
    __shared__ float sA[CIN * HD], sB[CIN * HD], sR[CIN * HD], sb[HD];
    for (int i = threadIdx.x; i < CIN * HD; i += 256) {
        sA[i] = w1l[ta * CIN * HD + i];
        sB[i] = w1l[tb * CIN * HD + i];
        sR[i] = w1r[ta * CIN * HD + i] + w1r[tb * CIN * HD + i];
    }
    if (threadIdx.x < HD)
        sb[threadIdx.x] = b1l[ta * HD + threadIdx.x] + b1l[tb * HD + threadIdx.x];
    __syncthreads();

    int n = blockIdx.x * 256 + threadIdx.x;
    if (n >= NSN) return;

    float acc[HD];
    #pragma unroll
    for (int o = 0; o < HD; o++) acc[o] = sb[o];

    const float* A = g_mean1[ta] + (size_t)n * CIN;
    const float* B = g_mean1[tb] + (size_t)n * CIN;
    const float* X = x + (size_t)n * CIN;
    #pragma unroll
    for (int i = 0; i < CIN; i++) {
        float ma = A[i], mb = B[i], xv = X[i];
        const float4* wa = (const float4*)(sA + i * HD);
        const float4* wb = (const float4*)(sB + i * HD);
        const float4* wr = (const float4*)(sR + i * HD);
        #pragma unroll
        for (int o4 = 0; o4 < HD / 4; o4++) {
            float4 a = wa[o4], b = wb[o4], r = wr[o4];
            acc[o4 * 4 + 0] += ma * a.x + mb * b.x + xv * r.x;
            acc[o4 * 4 + 1] += ma * a.y + mb * b.y + xv * r.y;
            acc[o4 * 4 + 2] += ma * a.z + mb * b.z + xv * r.z;
            acc[o4 * 4 + 3] += ma * a.w + mb * b.w + xv * r.w;
        }
    }
    float4* out = (float4*)(g_h[nt] + (size_t)n * HD);
    #pragma unroll
    for (int o4 = 0; o4 < HD / 4; o4++) {
        float4 v;
        v.x = fmaxf(acc[o4 * 4 + 0], 0.f);
        v.y = fmaxf(acc[o4 * 4 + 1], 0.f);
        v.z = fmaxf(acc[o4 * 4 + 2], 0.f);
        v.w = fmaxf(acc[o4 * 4 + 3], 0.f);
        out[o4] = v;
    }
}

// ---------------- coalesced fp32 -> bf16 conversion of g_h -------------------
__global__ void __launch_bounds__(256) k_tobf16() {
    int i = blockIdx.x * 256 + threadIdx.x;   // indexes bfloat162 elements
    const int TOT = NSN * HD / 2;             // per node type
    if (i >= TOT) return;
    float2 v0 = ((const float2*)g_h[0])[i];
    float2 v1 = ((const float2*)g_h[1])[i];
    ((__nv_bfloat162*)g_hbf[0])[i] = __floats2bfloat162_rn(v0.x, v0.y);
    ((__nv_bfloat162*)g_hbf[1])[i] = __floats2bfloat162_rn(v1.x, v1.y);
}

// ---------------- layer-2 gather-aggregate (bf16, warp per node,type) -------
__global__ void __launch_bounds__(256) k_agg2() {
    int t = blockIdx.y;
    int stype = t >> 1;
    int warp = threadIdx.x >> 5, lane = threadIdx.x & 31;
    int n = blockIdx.x * 8 + warp;
    if (n >= NSN) return;
    int base = g_rowstart[t][n];
    int cnt = g_hist[t][n];
    const int* cs = g_csr[t] + base;
    const __nv_bfloat162* h2 = (const __nv_bfloat162*)g_hbf[stype];  // row stride 32
    float a0 = 0.f, a1 = 0.f;
    int i = 0;
    for (; i + 4 <= cnt; i += 4) {
        int s0 = cs[i], s1 = cs[i + 1], s2 = cs[i + 2], s3 = cs[i + 3];
        __nv_bfloat162 v0 = h2[(size_t)s0 * 32 + lane];
        __nv_bfloat162 v1 = h2[(size_t)s1 * 32 + lane];
        __nv_bfloat162 v2 = h2[(size_t)s2 * 32 + lane];
        __nv_bfloat162 v3 = h2[(size_t)s3 * 32 + lane];
        a0 += __low2float(v0) + __low2float(v1) + __low2float(v2) + __low2float(v3);
        a1 += __high2float(v0) + __high2float(v1) + __high2float(v2) + __high2float(v3);
    }
    for (; i < cnt; i++) {
        __nv_bfloat162 v = h2[(size_t)cs[i] * 32 + lane];
        a0 += __low2float(v);
        a1 += __high2float(v);
    }
    float inv = 1.f / (float)(cnt > 0 ? cnt : 1);
    float2 m; m.x = a0 * inv; m.y = a1 * inv;
    ((float2*)(g_mean2[t] + (size_t)n * HD))[lane] = m;
}

// ---------------- layer-2 node update ---------------------------------------
__global__ void __launch_bounds__(256) k_l2nodes(const float* __restrict__ w2l,
                                                 const float* __restrict__ b2l,
                                                 const float* __restrict__ w2r) {
    int nt = blockIdx.y;
    int ta = nt ? 1 : 0;
    int tb = nt ? 3 : 2;
    __shared__ float sA[HD * HD], sB[HD * HD], sR[HD * HD];
    for (int i = threadIdx.x; i < HD * HD; i += 256) {
        sA[i] = w2l[ta * HD * HD + i];
        sB[i] = w2l[tb * HD * HD + i];
        sR[i] = w2r[ta * HD * HD + i] + w2r[tb * HD * HD + i];
    }
    __syncthreads();

    int n = blockIdx.x * 256 + threadIdx.x;
    if (n >= NSN) return;

    float acc[HD];
    #pragma unroll
    for (int o = 0; o < HD; o++) acc[o] = b2l[ta * HD + o] + b2l[tb * HD + o];

    const float4* A4 = (const float4*)(g_mean2[ta] + (size_t)n * HD);
    const float4* B4 = (const float4*)(g_mean2[tb] + (size_t)n * HD);
    const float4* H4 = (const float4*)(g_h[nt] + (size_t)n * HD);

    #pragma unroll
    for (int g = 0; g < HD / 4; g++) {
        float4 mav = A4[g], mbv = B4[g], hhv = H4[g];
        float fa[4] = {mav.x, mav.y, mav.z, mav.w};
        float fb[4] = {mbv.x, mbv.y, mbv.z, mbv.w};
        float fh[4] = {hhv.x, hhv.y, hhv.z, hhv.w};
        #pragma unroll
        for (int u = 0; u < 4; u++) {
            int k = g * 4 + u;
            const float4* wa = (const float4*)(sA + k * HD);
            const float4* wb = (const float4*)(sB + k * HD);
            const float4* wr = (const float4*)(sR + k * HD);
            #pragma unroll
            for (int o4 = 0; o4 < HD / 4; o4++) {
                float4 a = wa[o4], b = wb[o4], r = wr[o4];
                acc[o4 * 4 + 0] += fa[u] * a.x + fb[u] * b.x + fh[u] * r.x;
                acc[o4 * 4 + 1] += fa[u] * a.y + fb[u] * b.y + fh[u] * r.y;
                acc[o4 * 4 + 2] += fa[u] * a.z + fb[u] * b.z + fh[u] * r.z;
                acc[o4 * 4 + 3] += fa[u] * a.w + fb[u] * b.w + fh[u] * r.w;
            }
        }
    }
    float4* out = (float4*)(g_h2[nt] + (size_t)n * HD);
    #pragma unroll
    for (int o4 = 0; o4 < HD / 4; o4++) {
        float4 v;
        v.x = fmaxf(acc[o4 * 4 + 0], 0.f);
        v.y = fmaxf(acc[o4 * 4 + 1], 0.f);
        v.z = fmaxf(acc[o4 * 4 + 2], 0.f);
        v.w = fmaxf(acc[o4 * 4 + 3], 0.f);
        out[o4] = v;
    }
}

// ---------------- final linear heads ----------------------------------------
__global__ void k_final(const float* __restrict__ wls, const float* __restrict__ bls,
                        const float* __restrict__ wlp, const float* __restrict__ blp,
                        float* __restrict__ out) {
    int n = blockIdx.x * 256 + threadIdx.x;
    if (n >= 2 * NSN) return;
    int nt = (n < NSN) ? 0 : 1;
    int m = nt ? n - NSN : n;
    const float4* h4 = (const float4*)(g_h2[nt] + (size_t)m * HD);
    const float* w = nt ? wlp : wls;
    float acc = nt ? blp[0] : bls[0];
    #pragma unroll
    for (int g = 0; g < 16; g++) {
        float4 v = h4[g];
        acc += v.x * w[g * 4] + v.y * w[g * 4 + 1] + v.z * w[g * 4 + 2] + v.w * w[g * 4 + 3];
    }
    out[n] = acc;
}

// ---------------- launch ----------------------------------------------------
extern "C" void kernel_launch(void* const* d_in, const int* in_sizes, int n_in,
                              void* d_out, int out_size) {
    const float* xs  = (const float*)d_in[0];
    const float* xp  = (const float*)d_in[1];
    const float* w1l = (const float*)d_in[2];
    const float* b1l = (const float*)d_in[3];
    const float* w1r = (const float*)d_in[4];
    const float* w2l = (const float*)d_in[5];
    const float* b2l = (const float*)d_in[6];
    const float* w2r = (const float*)d_in[7];
    const float* wls = (const float*)d_in[8];
    const float* bls = (const float*)d_in[9];
    const float* wlp = (const float*)d_in[10];
    const float* blp = (const float*)d_in[11];
    const int* ss = (const int*)d_in[12];
    const int* sp = (const int*)d_in[13];
    const int* ps = (const int*)d_in[14];
    const int* pp = (const int*)d_in[15];
    float* out = (float*)d_out;

    k_zero_hist<<<(NSN + 255) / 256, 256>>>();
    k_hist<<<NE / 256, 256>>>(ss + NE, sp + NE, ps + NE, pp + NE);
    k_bsum<<<dim3(NBLK, 4), 256>>>();
    k_sb<<<1, 256>>>();
    k_scan2<<<dim3(NBLK, 4), 256>>>();
    k_fill<<<dim3(NE / 256, 4), 256>>>(ss, sp, ps, pp);
    k_agg1<<<dim3((NSN + 7) / 8, 4), 256>>>(xs, xp);
    k_l1nodes<<<dim3((NSN + 255) / 256, 2), 256>>>(xs, xp, w1l, b1l, w1r);
    k_tobf16<<<(NSN * HD / 2 + 255) / 256, 256>>>();
    k_agg2<<<dim3((NSN + 7) / 8, 4), 256>>>();
    k_l2nodes<<<dim3((NSN + 255) / 256, 2), 256>>>(w2l, b2l, w2r);
    k_final<<<(2 * NSN + 255) / 256, 256>>>(wls, bls, wlp, blp, out);
}